// round 12
// baseline (speedup 1.0000x reference)
#include <cuda_runtime.h>
#include <stdint.h>

// Batched upper-triangular scatter:
//   out[b, r, c] = in[b, r*M - r*(r-1)/2 + (c-r)]  if c >= r, else 0
// M = 1024, TRIU = 524800, B = 128.
//
// Pure bandwidth kernel at the traffic floor (256 MiB read + 512 MiB write).
// R12: persistent-CTA variant of the champion. 1184 resident CTAs
// (148 SMs x 8) grid-stride over the 32768 row-tiles in the champion's
// scheduling order (row-tiles fastest within a batch). Warps stay alive
// across ~28 tiles: next tile's loads overlap current tile's store drain,
// and wave-transition overhead vanishes. Data path identical to champion
// (__ldcs front-batched MLP=4 float4 loads, __stcs float4 stores).

#define MAT_M 1024
#define TRIU_LEN 524800
#define ROWS_PER_BLK 4
#define TILES_PER_BATCH (MAT_M / ROWS_PER_BLK)   // 256

__device__ __forceinline__ float4 ldcs4(const float* p) {
    float4 v;
    v.x = __ldcs(p + 0);
    v.y = __ldcs(p + 1);
    v.z = __ldcs(p + 2);
    v.w = __ldcs(p + 3);
    return v;
}

__global__ void __launch_bounds__(256, 8)
triu_scatter_kernel(const float* __restrict__ in, float* __restrict__ out,
                    int n_tiles)
{
    const int c0 = threadIdx.x << 2;            // 0,4,...,1020

    for (int t = blockIdx.x; t < n_tiles; t += gridDim.x) {
        // Champion ordering: row-tile fastest within a batch.
        const int b  = t / TILES_PER_BATCH;
        const int r0 = (t - b * TILES_PER_BATCH) * ROWS_PER_BLK;

        const float* __restrict__ inb = in + (size_t)b * TRIU_LEN;

        float4 v[ROWS_PER_BLK];

        // ---- Phase 1: batch all loads (independent -> MLP=4) ----
        #pragma unroll
        for (int j = 0; j < ROWS_PER_BLK; ++j) {
            const int r = r0 + j;
            // rowstart = r*M - r*(r-1)/2, max 524799 (fits int)
            const int rowstart = r * MAT_M - ((r * (r - 1)) >> 1);

            if (c0 >= r) {
                // Fully inside upper triangle: contiguous packed load.
                v[j] = ldcs4(inb + rowstart + (c0 - r));
            } else if (c0 + 3 < r) {
                // Fully below diagonal: pure zero store, no read.
                v[j] = make_float4(0.f, 0.f, 0.f, 0.f);
            } else {
                // Straddles the diagonal (<=1 thread per row).
                float t4[4];
                #pragma unroll
                for (int k = 0; k < 4; ++k) {
                    const int c = c0 + k;
                    t4[k] = (c >= r) ? __ldcs(inb + rowstart + (c - r)) : 0.f;
                }
                v[j] = make_float4(t4[0], t4[1], t4[2], t4[3]);
            }
        }

        // ---- Phase 2: aligned streaming float4 stores ----
        const size_t base = (((size_t)b * MAT_M + (size_t)r0) * MAT_M) + (size_t)c0;
        #pragma unroll
        for (int j = 0; j < ROWS_PER_BLK; ++j) {
            __stcs(reinterpret_cast<float4*>(out + base + (size_t)j * MAT_M), v[j]);
        }
    }
}

extern "C" void kernel_launch(void* const* d_in, const int* in_sizes, int n_in,
                              void* d_out, int out_size)
{
    const float* in = (const float*)d_in[0];
    float* out = (float*)d_out;

    const int B = in_sizes[0] / TRIU_LEN;       // 128 for the bench shape
    const int n_tiles = B * TILES_PER_BATCH;    // 32768

    const int n_blocks = 148 * 8;               // one full resident wave
    dim3 grid(n_blocks < n_tiles ? n_blocks : n_tiles);
    dim3 block(256);
    triu_scatter_kernel<<<grid, block>>>(in, out, n_tiles);
}

// round 13
// speedup vs baseline: 1.1805x; 1.1805x over previous
#include <cuda_runtime.h>
#include <stdint.h>

// Batched upper-triangular scatter:
//   out[b, r, c] = in[b, r*M - r*(r-1)/2 + (c-r)]  if c >= r, else 0
// M = 1024, TRIU = 524800, B = 128.
//
// FINAL (converged champion). Pure bandwidth kernel at the traffic floor:
// 256 MiB read (packed rows abut -> input read exactly once, contiguously)
// + 512 MiB write (every output byte mandatory; harness poisons d_out).
// Config: 4 rows per 256-thread block, front-batched MLP=4 float4 loads,
// streaming (.cs) loads+stores, row-major CTA order (locality wins).
// Measured 81-82% of DRAM peak (~6.5 TB/s) = the mixed 1:2 R:W HBM
// turnaround ceiling; ten controlled variants (MLP depth, occupancy,
// cache policy, store width, block size, CTA ordering, persistent CTAs)
// all landed at or below this.

#define MAT_M 1024
#define TRIU_LEN 524800
#define ROWS_PER_BLK 4

__device__ __forceinline__ float4 ldcs4(const float* p) {
    float4 v;
    v.x = __ldcs(p + 0);
    v.y = __ldcs(p + 1);
    v.z = __ldcs(p + 2);
    v.w = __ldcs(p + 3);
    return v;
}

__global__ void __launch_bounds__(256, 8)
triu_scatter_kernel(const float* __restrict__ in, float* __restrict__ out)
{
    const int r0 = blockIdx.x * ROWS_PER_BLK;   // 0,4,...,1020
    const int b  = blockIdx.y;                  // 0..B-1
    const int c0 = threadIdx.x << 2;            // 0,4,...,1020

    const float* __restrict__ inb = in + (size_t)b * TRIU_LEN;

    float4 v[ROWS_PER_BLK];

    // ---- Phase 1: batch all loads (independent -> MLP=4) ----
    #pragma unroll
    for (int j = 0; j < ROWS_PER_BLK; ++j) {
        const int r = r0 + j;
        // rowstart = r*M - r*(r-1)/2, max 524799 (fits int)
        const int rowstart = r * MAT_M - ((r * (r - 1)) >> 1);

        if (c0 >= r) {
            // Fully inside upper triangle: contiguous packed load.
            v[j] = ldcs4(inb + rowstart + (c0 - r));
        } else if (c0 + 3 < r) {
            // Fully below diagonal: pure zero store, no read.
            v[j] = make_float4(0.f, 0.f, 0.f, 0.f);
        } else {
            // Straddles the diagonal (<=1 thread per row).
            float t[4];
            #pragma unroll
            for (int k = 0; k < 4; ++k) {
                const int c = c0 + k;
                t[k] = (c >= r) ? __ldcs(inb + rowstart + (c - r)) : 0.f;
            }
            v[j] = make_float4(t[0], t[1], t[2], t[3]);
        }
    }

    // ---- Phase 2: aligned streaming float4 stores ----
    const size_t base = (((size_t)b * MAT_M + (size_t)r0) * MAT_M) + (size_t)c0;
    #pragma unroll
    for (int j = 0; j < ROWS_PER_BLK; ++j) {
        __stcs(reinterpret_cast<float4*>(out + base + (size_t)j * MAT_M), v[j]);
    }
}

extern "C" void kernel_launch(void* const* d_in, const int* in_sizes, int n_in,
                              void* d_out, int out_size)
{
    const float* in = (const float*)d_in[0];
    float* out = (float*)d_out;

    const int B = in_sizes[0] / TRIU_LEN;   // 128 for the bench shape

    dim3 grid(MAT_M / ROWS_PER_BLK, B);
    dim3 block(256);
    triu_scatter_kernel<<<grid, block>>>(in, out);
}

// round 14
// speedup vs baseline: 1.1877x; 1.0061x over previous
#include <cuda_runtime.h>
#include <stdint.h>

// Batched upper-triangular scatter:
//   out[b, r, c] = in[b, r*M - r*(r-1)/2 + (c-r)]  if c >= r, else 0
// M = 1024, TRIU = 524800, B = 128.
//
// FINAL (converged champion, reproduced 3x at 120.9-121.6 us wall).
// Pure bandwidth kernel at the traffic floor: 256 MiB read (packed rows
// abut -> input read exactly once, contiguously) + 512 MiB write (every
// output byte mandatory; harness poisons d_out). Config: 4 rows per
// 256-thread block, front-batched MLP=4 float4 loads, streaming (.cs)
// loads+stores, row-major CTA order. Measured 81-82% of DRAM peak
// (~6.5 TB/s) = the mixed 1:2 R:W HBM turnaround ceiling; ten controlled
// variants (MLP depth, occupancy, cache policy, store width, block size,
// CTA ordering, persistent CTAs) all landed at or below this.

#define MAT_M 1024
#define TRIU_LEN 524800
#define ROWS_PER_BLK 4

__device__ __forceinline__ float4 ldcs4(const float* p) {
    float4 v;
    v.x = __ldcs(p + 0);
    v.y = __ldcs(p + 1);
    v.z = __ldcs(p + 2);
    v.w = __ldcs(p + 3);
    return v;
}

__global__ void __launch_bounds__(256, 8)
triu_scatter_kernel(const float* __restrict__ in, float* __restrict__ out)
{
    const int r0 = blockIdx.x * ROWS_PER_BLK;   // 0,4,...,1020
    const int b  = blockIdx.y;                  // 0..B-1
    const int c0 = threadIdx.x << 2;            // 0,4,...,1020

    const float* __restrict__ inb = in + (size_t)b * TRIU_LEN;

    float4 v[ROWS_PER_BLK];

    // ---- Phase 1: batch all loads (independent -> MLP=4) ----
    #pragma unroll
    for (int j = 0; j < ROWS_PER_BLK; ++j) {
        const int r = r0 + j;
        // rowstart = r*M - r*(r-1)/2, max 524799 (fits int)
        const int rowstart = r * MAT_M - ((r * (r - 1)) >> 1);

        if (c0 >= r) {
            // Fully inside upper triangle: contiguous packed load.
            v[j] = ldcs4(inb + rowstart + (c0 - r));
        } else if (c0 + 3 < r) {
            // Fully below diagonal: pure zero store, no read.
            v[j] = make_float4(0.f, 0.f, 0.f, 0.f);
        } else {
            // Straddles the diagonal (<=1 thread per row).
            float t[4];
            #pragma unroll
            for (int k = 0; k < 4; ++k) {
                const int c = c0 + k;
                t[k] = (c >= r) ? __ldcs(inb + rowstart + (c - r)) : 0.f;
            }
            v[j] = make_float4(t[0], t[1], t[2], t[3]);
        }
    }

    // ---- Phase 2: aligned streaming float4 stores ----
    const size_t base = (((size_t)b * MAT_M + (size_t)r0) * MAT_M) + (size_t)c0;
    #pragma unroll
    for (int j = 0; j < ROWS_PER_BLK; ++j) {
        __stcs(reinterpret_cast<float4*>(out + base + (size_t)j * MAT_M), v[j]);
    }
}

extern "C" void kernel_launch(void* const* d_in, const int* in_sizes, int n_in,
                              void* d_out, int out_size)
{
    const float* in = (const float*)d_in[0];
    float* out = (float*)d_out;

    const int B = in_sizes[0] / TRIU_LEN;   // 128 for the bench shape

    dim3 grid(MAT_M / ROWS_PER_BLK, B);
    dim3 block(256);
    triu_scatter_kernel<<<grid, block>>>(in, out);
}